// round 12
// baseline (speedup 1.0000x reference)
#include <cuda_runtime.h>
#include <cuda_bf16.h>
#include <cstdint>

#define SCORE_THRESH 0.2f
#define NMS_THRESH   0.5f
#define MAXH 15
#define MAXO 15
#define KOUT 30
#define NCLS 81
#define G    4            // CTAs per batch
#define NJ   21           // classes per CTA = ceil(81/4)
#define CAP  64           // per-class capacity (mean ~20, 64 ≈ 9.7 sigma)
#define BMAX 64
#define NOBJ (NCLS - 1)   // 80 object classes
#define NOKEYS (NOBJ * MAXO)   // 1200
#define NTHREADS 672

typedef unsigned long long u64;

// Scratch kept-keys per (batch, class); slots zero-padded every run.
__device__ u64 g_keys[BMAX * NCLS * MAXO];
// Arrival counters; never reset — each launch adds exactly G per batch, so
// (old % G == G-1) identifies the last CTA on every launch/replay.
__device__ unsigned int g_done[BMAX];

__global__ __launch_bounds__(NTHREADS, 1)
void fused_kernel(const float* __restrict__ boxes,
                  const float* __restrict__ scores,
                  const int*   __restrict__ labels,
                  float* __restrict__ out,
                  int B, int N)
{
    __shared__ u64 bucket[NJ * CAP];
    __shared__ u64 allkeys[NOKEYS];     // merge staging (last CTA only)
    __shared__ int bcnt[NJ];
    __shared__ int isLast;

    const int g    = blockIdx.x;        // class group (c % G == g)
    const int b    = blockIdx.y;
    const int tid  = threadIdx.x;
    const int wid  = tid >> 5;
    const int lane = tid & 31;
    const unsigned FULL = 0xFFFFFFFFu;

    const float4* bx4 = (const float4*)(boxes + (size_t)b * N * 4);
    const float4* sc4 = (const float4*)(scores + (size_t)b * N);
    const int4*   lb4 = (const int4*)(labels + (size_t)b * N);

    float* outBoxes  = out;                          // [B][KOUT][4]
    float* outScores = out + (size_t)B * KOUT * 4;
    float* outLabels = out + (size_t)B * KOUT * 5;
    float* outValid  = out + (size_t)B * KOUT * 6;

    if (tid < NJ) bcnt[tid] = 0;
    __syncthreads();

    // ---- Phase A: vectorized scan + scatter keys of our class group ----
    for (int i4 = tid; i4 * 4 < N; i4 += NTHREADS) {
        float4 s = sc4[i4];
        int4   l = lb4[i4];
        int i0 = i4 * 4;
        #pragma unroll
        for (int e = 0; e < 4; e++) {
            float se = (e == 0) ? s.x : (e == 1) ? s.y : (e == 2) ? s.z : s.w;
            int   le = (e == 0) ? l.x : (e == 1) ? l.y : (e == 2) ? l.z : l.w;
            if (se >= SCORE_THRESH && (le & (G - 1)) == g) {
                int j = le >> 2;
                u64 k = ((u64)__float_as_uint(se) << 32) |
                        ((u64)(unsigned)(i0 + e) << 8) | (unsigned)le;
                int p = atomicAdd(&bcnt[j], 1);
                if (p < CAP) bucket[j * CAP + p] = k;
            }
        }
    }
    __syncthreads();

    // ---- Phase B: one class per warp — selection-based greedy NMS (no sort) ----
    const int  c  = wid * G + g;
    const bool vc = (c < NCLS);
    int cnt = vc ? min(bcnt[wid], CAP) : 0;

    u64   wkey = 0;                                  // lane r: r-th kept key
    float wbx1 = 0, wby1 = 0, wbx2 = 0, wby2 = 0;    // lane r: r-th kept box

    if (cnt > 0) {
        // candidates: 2 per lane, unsorted (bucket order is irrelevant)
        u64 k0 = (lane      < cnt) ? bucket[wid * CAP + lane]      : 0ull;
        u64 k1 = (lane + 32 < cnt) ? bucket[wid * CAP + lane + 32] : 0ull;
        bool a0 = (lane < cnt), a1 = (lane + 32 < cnt);

        // parallel box prefetch
        float4 mb0 = make_float4(0, 0, 0, 0), mb1 = make_float4(0, 0, 0, 0);
        if (a0) mb0 = bx4[(int)((k0 >> 8) & 0xFFFFFFull)];
        if (a1) mb1 = bx4[(int)((k1 >> 8) & 0xFFFFFFull)];
        float ar0 = (mb0.z - mb0.x) * (mb0.w - mb0.y);
        float ar1 = (mb1.z - mb1.x) * (mb1.w - mb1.y);

        for (int r = 0; r < MAXO; r++) {
            u64 c0 = a0 ? k0 : 0ull;
            u64 c1 = a1 ? k1 : 0ull;
            u64 lmax = max(c0, c1);
            unsigned hi = (unsigned)(lmax >> 32);
            unsigned mh = __reduce_max_sync(FULL, hi);
            if (mh == 0u) break;                       // no alive candidates
            unsigned lo = (hi == mh) ? (unsigned)lmax : 0u;
            unsigned ml = __reduce_max_sync(FULL, lo);
            u64 win = ((u64)mh << 32) | ml;

            // broadcast winner's box from its owner lane
            int have = (c0 == win) ? 0 : ((c1 == win) ? 1 : -1);
            unsigned bal = __ballot_sync(FULL, have >= 0);
            int src = __ffs(bal) - 1;
            float wx1 = (have == 1) ? mb1.x : mb0.x;
            float wy1 = (have == 1) ? mb1.y : mb0.y;
            float wx2 = (have == 1) ? mb1.z : mb0.z;
            float wy2 = (have == 1) ? mb1.w : mb0.w;
            wx1 = __shfl_sync(FULL, wx1, src);
            wy1 = __shfl_sync(FULL, wy1, src);
            wx2 = __shfl_sync(FULL, wx2, src);
            wy2 = __shfl_sync(FULL, wy2, src);

            if (lane == r) { wkey = win; wbx1 = wx1; wby1 = wy1; wbx2 = wx2; wby2 = wy2; }

            // suppress: alive candidates overlapping winner die (incl. winner, IoU=1)
            float aW = (wx2 - wx1) * (wy2 - wy1);
            if (a0) {
                float ltx = fmaxf(mb0.x, wx1), lty = fmaxf(mb0.y, wy1);
                float rbx = fminf(mb0.z, wx2), rby = fminf(mb0.w, wy2);
                float inter = fmaxf(rbx - ltx, 0.0f) * fmaxf(rby - lty, 0.0f);
                if (inter / (ar0 + aW - inter + 1e-9f) > NMS_THRESH) a0 = false;
            }
            if (a1) {
                float ltx = fmaxf(mb1.x, wx1), lty = fmaxf(mb1.y, wy1);
                float rbx = fminf(mb1.z, wx2), rby = fminf(mb1.w, wy2);
                float inter = fmaxf(rbx - ltx, 0.0f) * fmaxf(rby - lty, 0.0f);
                if (inter / (ar1 + aW - inter + 1e-9f) > NMS_THRESH) a1 = false;
            }
        }
    }

    if (vc) {
        if (c == 0) {
            // humans: slots 0..14 (incl. defaults) straight from registers
            if (lane < MAXH) {
                bool v = (wkey != 0ull);
                float* ob = outBoxes + ((size_t)b * KOUT + lane) * 4;
                *(float4*)ob = v ? make_float4(wbx1, wby1, wbx2, wby2)
                                 : make_float4(0, 0, 0, 0);
                outScores[b * KOUT + lane] = v ? __uint_as_float((unsigned)(wkey >> 32)) : 0.0f;
                outLabels[b * KOUT + lane] = v ? 0.0f : -1.0f;
                outValid [b * KOUT + lane] = v ? 1.0f : 0.0f;
            }
        } else {
            if (lane < MAXO)
                g_keys[((size_t)b * NCLS + c) * MAXO + lane] = wkey;
        }
    }

    // ---- last-CTA election (threadFenceReduction pattern) ----
    __syncthreads();
    if (tid == 0) {
        __threadfence();
        unsigned old = atomicAdd(&g_done[b], 1u);
        isLast = ((old & (G - 1)) == (G - 1)) ? 1 : 0;
        if (isLast) __threadfence();
    }
    __syncthreads();
    if (!isLast) return;

    // ---- merge (last CTA): stage 1200 keys, redux tournament top-15 ----
    const size_t bb = (size_t)b * NCLS * MAXO;
    for (int i = tid; i < NOKEYS; i += NTHREADS) allkeys[i] = g_keys[bb + MAXO + i];
    __syncthreads();

    if (tid < 32) {
        const int l0 = lane, l1 = lane + 32, l2 = lane + 64;
        u64 h0 = allkeys[l0 * MAXO];
        u64 h1 = allkeys[l1 * MAXO];
        u64 h2 = (lane < 16) ? allkeys[l2 * MAXO] : 0ull;
        int p0 = 0, p1 = 0, p2 = 0;

        u64 mkey = 0;
        for (int r = 0; r < MAXO; r++) {
            u64 lmax = max(h0, max(h1, h2));
            unsigned hi = (unsigned)(lmax >> 32);
            unsigned mh = __reduce_max_sync(FULL, hi);
            unsigned lo = (hi == mh) ? (unsigned)lmax : 0u;
            unsigned ml = __reduce_max_sync(FULL, lo);
            u64 win = ((u64)mh << 32) | ml;
            if (win == 0ull) break;
            if (lane == r) mkey = win;
            if (h0 == win)      { p0++; h0 = (p0 < MAXO) ? allkeys[l0 * MAXO + p0] : 0ull; }
            else if (h1 == win) { p1++; h1 = (p1 < MAXO) ? allkeys[l1 * MAXO + p1] : 0ull; }
            else if (h2 == win) { p2++; h2 = (p2 < MAXO) ? allkeys[l2 * MAXO + p2] : 0ull; }
        }

        if (lane < MAXO) {
            int slot = MAXH + lane;
            bool v = (mkey != 0ull);
            float4 wb = v ? bx4[(int)((mkey >> 8) & 0xFFFFFFull)]
                          : make_float4(0, 0, 0, 0);
            float* ob = outBoxes + ((size_t)b * KOUT + slot) * 4;
            *(float4*)ob = wb;
            outScores[b * KOUT + slot] = v ? __uint_as_float((unsigned)(mkey >> 32)) : 0.0f;
            outLabels[b * KOUT + slot] = v ? (float)(int)(mkey & 0xFFull) : -1.0f;
            outValid [b * KOUT + slot] = v ? 1.0f : 0.0f;
        }
    }
}

extern "C" void kernel_launch(void* const* d_in, const int* in_sizes, int n_in,
                              void* d_out, int out_size)
{
    const float* boxes  = (const float*)d_in[0];
    const float* scores = (const float*)d_in[1];
    const int*   labels = (const int*)d_in[2];

    int B = out_size / (KOUT * 7);        // 32
    if (B <= 0) B = 1;
    if (B > BMAX) B = BMAX;
    int N = in_sizes[1] / B;              // 2048

    dim3 grid(G, B);
    fused_kernel<<<grid, NTHREADS>>>(boxes, scores, labels, (float*)d_out, B, N);
}

// round 13
// speedup vs baseline: 1.2064x; 1.2064x over previous
#include <cuda_runtime.h>
#include <cuda_bf16.h>
#include <cstdint>

#define SCORE_THRESH 0.2f
#define NMS_THRESH   0.5f
#define MAXH 15
#define MAXO 15
#define KOUT 30
#define NCLS 81
#define G    4            // CTAs per batch
#define NJ   21           // classes per CTA = ceil(81/4)
#define CAP  64           // per-class capacity (mean ~20, 64 ≈ 9.7 sigma)
#define BMAX 64
#define NOBJ (NCLS - 1)   // 80 object classes
#define NOKEYS (NOBJ * MAXO)   // 1200
#define NTHREADS 672

typedef unsigned long long u64;

// Scratch kept-keys per (batch, class); all 15 slots written every run.
__device__ u64 g_keys[BMAX * NCLS * MAXO];
// Arrival counters; never reset — each launch adds exactly G per batch, so
// (old % G == G-1) identifies the last CTA on every launch/replay.
__device__ unsigned int g_done[BMAX];

__device__ __forceinline__ bool sup_test(const float4& m, float amine,
                                         float wx1, float wy1, float wx2, float wy2,
                                         float aW)
{
    float ltx = fmaxf(m.x, wx1), lty = fmaxf(m.y, wy1);
    float rbx = fminf(m.z, wx2), rby = fminf(m.w, wy2);
    float inter = fmaxf(rbx - ltx, 0.0f) * fmaxf(rby - lty, 0.0f);
    return inter / (amine + aW - inter + 1e-9f) > NMS_THRESH;
}

__global__ __launch_bounds__(NTHREADS, 1)
void fused_kernel(const float* __restrict__ boxes,
                  const float* __restrict__ scores,
                  const int*   __restrict__ labels,
                  float* __restrict__ out,
                  int B, int N)
{
    __shared__ u64 bucket[NJ * CAP];
    __shared__ u64 allkeys[NOKEYS];     // merge staging (last CTA only)
    __shared__ int bcnt[NJ];
    __shared__ int isLast;

    const int g    = blockIdx.x;        // class group (c % G == g)
    const int b    = blockIdx.y;
    const int tid  = threadIdx.x;
    const int wid  = tid >> 5;
    const int lane = tid & 31;
    const unsigned FULL = 0xFFFFFFFFu;

    const float4* bx4 = (const float4*)(boxes + (size_t)b * N * 4);
    const float4* sc4 = (const float4*)(scores + (size_t)b * N);
    const int4*   lb4 = (const int4*)(labels + (size_t)b * N);

    float* outBoxes  = out;                          // [B][KOUT][4]
    float* outScores = out + (size_t)B * KOUT * 4;
    float* outLabels = out + (size_t)B * KOUT * 5;
    float* outValid  = out + (size_t)B * KOUT * 6;

    if (tid < NJ) bcnt[tid] = 0;
    __syncthreads();

    // ---- Phase A: vectorized scan + scatter keys of our class group ----
    for (int i4 = tid; i4 * 4 < N; i4 += NTHREADS) {
        float4 s = sc4[i4];
        int4   l = lb4[i4];
        int i0 = i4 * 4;
        #pragma unroll
        for (int e = 0; e < 4; e++) {
            float se = (e == 0) ? s.x : (e == 1) ? s.y : (e == 2) ? s.z : s.w;
            int   le = (e == 0) ? l.x : (e == 1) ? l.y : (e == 2) ? l.z : l.w;
            if (se >= SCORE_THRESH && (le & (G - 1)) == g) {
                int j = le >> 2;
                u64 k = ((u64)__float_as_uint(se) << 32) |
                        ((u64)(unsigned)(i0 + e) << 8) | (unsigned)le;
                int p = atomicAdd(&bcnt[j], 1);
                if (p < CAP) bucket[j * CAP + p] = k;
            }
        }
    }
    __syncthreads();

    // ---- Phase B: one class per warp, sorted greedy NMS ----
    const int  c  = wid * G + g;
    const bool vc = (c < NCLS);
    int cnt = vc ? min(bcnt[wid], CAP) : 0;

    float kx1 = 0, ky1 = 0, kx2 = 0, ky2 = 0;   // kept box of rank `lane`
    float karea = 0;
    int   myT = -1;                             // sorted index kept at rank `lane`
    u64   mykey = 0;
    int   kC = 0;

    if (cnt > 0 && cnt <= 32) {
        // ---------- fast path: 32-wide register sort + lean greedy ----------
        u64 k0 = (lane < cnt) ? bucket[wid * CAP + lane] : 0ull;
        #pragma unroll
        for (int kk = 2; kk <= 32; kk <<= 1) {
            #pragma unroll
            for (int jj = kk >> 1; jj > 0; jj >>= 1) {
                u64 o = __shfl_xor_sync(FULL, k0, jj);
                bool lower = (lane & jj) == 0;
                bool d = (lane & kk) == 0;
                k0 = (lower == d) ? max(k0, o) : min(k0, o);
            }
        }
        float4 mb0 = make_float4(0, 0, 0, 0);
        if (lane < cnt) mb0 = bx4[(int)((k0 >> 8) & 0xFFFFFFull)];
        float ar0 = (mb0.z - mb0.x) * (mb0.w - mb0.y);

        for (int t = 0; t < cnt && kC < MAXO; t++) {
            float wx1 = __shfl_sync(FULL, mb0.x, t);
            float wy1 = __shfl_sync(FULL, mb0.y, t);
            float wx2 = __shfl_sync(FULL, mb0.z, t);
            float wy2 = __shfl_sync(FULL, mb0.w, t);
            float aW  = __shfl_sync(FULL, ar0,   t);
            bool sup = (lane < kC) &&
                sup_test(make_float4(kx1, ky1, kx2, ky2), karea, wx1, wy1, wx2, wy2, aW);
            if (!__any_sync(FULL, sup)) {
                if (lane == kC) { kx1 = wx1; ky1 = wy1; kx2 = wx2; ky2 = wy2;
                                  karea = aW; myT = t; }
                kC++;
            }
        }
        // deferred key fetch: one variable-source shuffle
        u64 kk0 = __shfl_sync(FULL, k0, (myT >= 0) ? myT : 0);
        mykey = (myT >= 0) ? kk0 : 0ull;
    } else if (cnt > 32) {
        // ---------- rare path: 64-wide sort, split greedy loops ----------
        u64 k0 = bucket[wid * CAP + lane];
        u64 k1 = (lane + 32 < cnt) ? bucket[wid * CAP + lane + 32] : 0ull;
        #pragma unroll
        for (int kk = 2; kk <= 64; kk <<= 1) {
            if (kk == 64) { if (k0 < k1) { u64 t = k0; k0 = k1; k1 = t; } }
            #pragma unroll
            for (int jj = (kk == 64) ? 16 : (kk >> 1); jj > 0; jj >>= 1) {
                bool lower = (lane & jj) == 0;
                u64 o0 = __shfl_xor_sync(FULL, k0, jj);
                u64 o1 = __shfl_xor_sync(FULL, k1, jj);
                bool d0 = ((lane)      & kk) == 0;
                bool d1 = ((lane + 32) & kk) == 0;
                k0 = (lower == d0) ? max(k0, o0) : min(k0, o0);
                k1 = (lower == d1) ? max(k1, o1) : min(k1, o1);
            }
        }
        float4 mb0 = bx4[(int)((k0 >> 8) & 0xFFFFFFull)];
        float4 mb1 = make_float4(0, 0, 0, 0);
        if (lane + 32 < cnt) mb1 = bx4[(int)((k1 >> 8) & 0xFFFFFFull)];
        float ar0 = (mb0.z - mb0.x) * (mb0.w - mb0.y);
        float ar1 = (mb1.z - mb1.x) * (mb1.w - mb1.y);

        for (int t = 0; t < 32 && kC < MAXO; t++) {
            float wx1 = __shfl_sync(FULL, mb0.x, t);
            float wy1 = __shfl_sync(FULL, mb0.y, t);
            float wx2 = __shfl_sync(FULL, mb0.z, t);
            float wy2 = __shfl_sync(FULL, mb0.w, t);
            float aW  = __shfl_sync(FULL, ar0,   t);
            bool sup = (lane < kC) &&
                sup_test(make_float4(kx1, ky1, kx2, ky2), karea, wx1, wy1, wx2, wy2, aW);
            if (!__any_sync(FULL, sup)) {
                if (lane == kC) { kx1 = wx1; ky1 = wy1; kx2 = wx2; ky2 = wy2;
                                  karea = aW; myT = t; }
                kC++;
            }
        }
        for (int t = 32; t < cnt && kC < MAXO; t++) {
            int sl = t - 32;
            float wx1 = __shfl_sync(FULL, mb1.x, sl);
            float wy1 = __shfl_sync(FULL, mb1.y, sl);
            float wx2 = __shfl_sync(FULL, mb1.z, sl);
            float wy2 = __shfl_sync(FULL, mb1.w, sl);
            float aW  = __shfl_sync(FULL, ar1,   sl);
            bool sup = (lane < kC) &&
                sup_test(make_float4(kx1, ky1, kx2, ky2), karea, wx1, wy1, wx2, wy2, aW);
            if (!__any_sync(FULL, sup)) {
                if (lane == kC) { kx1 = wx1; ky1 = wy1; kx2 = wx2; ky2 = wy2;
                                  karea = aW; myT = t; }
                kC++;
            }
        }
        int tA = (myT >= 0 && myT < 32) ? myT : 0;
        int tB = (myT >= 32) ? (myT - 32) : 0;
        u64 kA = __shfl_sync(FULL, k0, tA);
        u64 kB = __shfl_sync(FULL, k1, tB);
        mykey = (myT < 0) ? 0ull : ((myT < 32) ? kA : kB);
    }

    if (vc) {
        bool v = (myT >= 0);
        if (c == 0) {
            if (lane < MAXH) {
                float* ob = outBoxes + ((size_t)b * KOUT + lane) * 4;
                *(float4*)ob = v ? make_float4(kx1, ky1, kx2, ky2)
                                 : make_float4(0, 0, 0, 0);
                outScores[b * KOUT + lane] = v ? __uint_as_float((unsigned)(mykey >> 32)) : 0.0f;
                outLabels[b * KOUT + lane] = v ? 0.0f : -1.0f;
                outValid [b * KOUT + lane] = v ? 1.0f : 0.0f;
            }
        } else {
            if (lane < MAXO)
                g_keys[((size_t)b * NCLS + c) * MAXO + lane] = v ? mykey : 0ull;
        }
    }

    // ---- last-CTA election (threadFenceReduction pattern) ----
    __syncthreads();
    if (tid == 0) {
        __threadfence();
        unsigned old = atomicAdd(&g_done[b], 1u);
        isLast = ((old & (G - 1)) == (G - 1)) ? 1 : 0;
        if (isLast) __threadfence();
    }
    __syncthreads();
    if (!isLast) return;

    // ---- merge (last CTA): stage 1200 keys, redux tournament top-15 ----
    const size_t bb = (size_t)b * NCLS * MAXO;
    for (int i = tid; i < NOKEYS; i += NTHREADS) allkeys[i] = g_keys[bb + MAXO + i];
    __syncthreads();

    if (tid < 32) {
        const int l0 = lane, l1 = lane + 32, l2 = lane + 64;
        u64 h0 = allkeys[l0 * MAXO];
        u64 h1 = allkeys[l1 * MAXO];
        u64 h2 = (lane < 16) ? allkeys[l2 * MAXO] : 0ull;
        int p0 = 0, p1 = 0, p2 = 0;

        u64 mkey = 0;
        for (int r = 0; r < MAXO; r++) {
            u64 lmax = max(h0, max(h1, h2));
            unsigned hi = (unsigned)(lmax >> 32);
            unsigned mh = __reduce_max_sync(FULL, hi);
            unsigned lo = (hi == mh) ? (unsigned)lmax : 0u;
            unsigned ml = __reduce_max_sync(FULL, lo);
            u64 win = ((u64)mh << 32) | ml;
            if (win == 0ull) break;
            if (lane == r) mkey = win;
            if (h0 == win)      { p0++; h0 = (p0 < MAXO) ? allkeys[l0 * MAXO + p0] : 0ull; }
            else if (h1 == win) { p1++; h1 = (p1 < MAXO) ? allkeys[l1 * MAXO + p1] : 0ull; }
            else if (h2 == win) { p2++; h2 = (p2 < MAXO) ? allkeys[l2 * MAXO + p2] : 0ull; }
        }

        if (lane < MAXO) {
            int slot = MAXH + lane;
            bool v = (mkey != 0ull);
            float4 wb = v ? bx4[(int)((mkey >> 8) & 0xFFFFFFull)]
                          : make_float4(0, 0, 0, 0);
            float* ob = outBoxes + ((size_t)b * KOUT + slot) * 4;
            *(float4*)ob = wb;
            outScores[b * KOUT + slot] = v ? __uint_as_float((unsigned)(mkey >> 32)) : 0.0f;
            outLabels[b * KOUT + slot] = v ? (float)(int)(mkey & 0xFFull) : -1.0f;
            outValid [b * KOUT + slot] = v ? 1.0f : 0.0f;
        }
    }
}

extern "C" void kernel_launch(void* const* d_in, const int* in_sizes, int n_in,
                              void* d_out, int out_size)
{
    const float* boxes  = (const float*)d_in[0];
    const float* scores = (const float*)d_in[1];
    const int*   labels = (const int*)d_in[2];

    int B = out_size / (KOUT * 7);        // 32
    if (B <= 0) B = 1;
    if (B > BMAX) B = BMAX;
    int N = in_sizes[1] / B;              // 2048

    dim3 grid(G, B);
    fused_kernel<<<grid, NTHREADS>>>(boxes, scores, labels, (float*)d_out, B, N);
}

// round 14
// speedup vs baseline: 1.2534x; 1.0390x over previous
#include <cuda_runtime.h>
#include <cuda_bf16.h>
#include <cstdint>

#define SCORE_THRESH 0.2f
#define NMS_THRESH   0.5f
#define MAXH 15
#define MAXO 15
#define KOUT 30
#define NCLS 81
#define G    4            // CTAs per batch
#define NJ   21           // classes per CTA = ceil(81/4)
#define CAP  64           // per-class capacity (mean ~20, 64 ≈ 9.7 sigma)
#define BMAX 64
#define NOBJ (NCLS - 1)   // 80 object classes
#define NOKEYS (NOBJ * MAXO)   // 1200
#define NTHREADS 672

typedef unsigned long long u64;

// Scratch kept-keys per (batch, class); all 15 slots written every run.
__device__ u64 g_keys[BMAX * NCLS * MAXO];
// Arrival counters; never reset — each launch adds exactly G per batch, so
// (old % G == G-1) identifies the last CTA on every launch/replay.
__device__ unsigned int g_done[BMAX];

__global__ __launch_bounds__(NTHREADS, 1)
void fused_kernel(const float* __restrict__ boxes,
                  const float* __restrict__ scores,
                  const int*   __restrict__ labels,
                  float* __restrict__ out,
                  int B, int N)
{
    __shared__ u64    bucket[NJ * CAP];     // keys, then sorted keys
    __shared__ float4 sboxes[NJ * CAP];     // sorted candidate boxes
    __shared__ u64    allkeys[NOKEYS];      // merge staging (last CTA only)
    __shared__ int    bcnt[NJ];
    __shared__ int    isLast;

    const int g    = blockIdx.x;        // class group (c % G == g)
    const int b    = blockIdx.y;
    const int tid  = threadIdx.x;
    const int wid  = tid >> 5;
    const int lane = tid & 31;
    const unsigned FULL = 0xFFFFFFFFu;

    const float4* bx4 = (const float4*)(boxes + (size_t)b * N * 4);
    const float4* sc4 = (const float4*)(scores + (size_t)b * N);
    const int4*   lb4 = (const int4*)(labels + (size_t)b * N);

    float* outBoxes  = out;                          // [B][KOUT][4]
    float* outScores = out + (size_t)B * KOUT * 4;
    float* outLabels = out + (size_t)B * KOUT * 5;
    float* outValid  = out + (size_t)B * KOUT * 6;

    if (tid < NJ) bcnt[tid] = 0;
    __syncthreads();

    // ---- Phase A: vectorized scan + scatter keys of our class group ----
    for (int i4 = tid; i4 * 4 < N; i4 += NTHREADS) {
        float4 s = sc4[i4];
        int4   l = lb4[i4];
        int i0 = i4 * 4;
        #pragma unroll
        for (int e = 0; e < 4; e++) {
            float se = (e == 0) ? s.x : (e == 1) ? s.y : (e == 2) ? s.z : s.w;
            int   le = (e == 0) ? l.x : (e == 1) ? l.y : (e == 2) ? l.z : l.w;
            if (se >= SCORE_THRESH && (le & (G - 1)) == g) {
                int j = le >> 2;
                u64 k = ((u64)__float_as_uint(se) << 32) |
                        ((u64)(unsigned)(i0 + e) << 8) | (unsigned)le;
                int p = atomicAdd(&bcnt[j], 1);
                if (p < CAP) bucket[j * CAP + p] = k;
            }
        }
    }
    __syncthreads();

    // ---- Phase B: one class per warp, sorted greedy NMS (LDS broadcast) ----
    const int  c  = wid * G + g;
    const bool vc = (c < NCLS);
    int cnt = vc ? min(bcnt[wid], CAP) : 0;

    float kx1 = 0, ky1 = 0, kx2 = 0, ky2 = 0;   // kept box of rank `lane`
    float karea = 0;
    int   myT = -1;                             // sorted index kept at rank `lane`
    int   kC = 0;

    if (cnt > 0) {
        if (cnt <= 32) {
            // fast path: 32-wide register sort
            u64 k0 = (lane < cnt) ? bucket[wid * CAP + lane] : 0ull;
            #pragma unroll
            for (int kk = 2; kk <= 32; kk <<= 1) {
                #pragma unroll
                for (int jj = kk >> 1; jj > 0; jj >>= 1) {
                    u64 o = __shfl_xor_sync(FULL, k0, jj);
                    bool lower = (lane & jj) == 0;
                    bool d = (lane & kk) == 0;
                    k0 = (lower == d) ? max(k0, o) : min(k0, o);
                }
            }
            float4 mb0 = make_float4(0, 0, 0, 0);
            if (lane < cnt) mb0 = bx4[(int)((k0 >> 8) & 0xFFFFFFull)];
            bucket[wid * CAP + lane] = k0;
            sboxes[wid * CAP + lane] = mb0;
        } else {
            // rare path: 64-wide sort, 2 keys/lane
            u64 k0 = bucket[wid * CAP + lane];
            u64 k1 = (lane + 32 < cnt) ? bucket[wid * CAP + lane + 32] : 0ull;
            #pragma unroll
            for (int kk = 2; kk <= 64; kk <<= 1) {
                if (kk == 64) { if (k0 < k1) { u64 t = k0; k0 = k1; k1 = t; } }
                #pragma unroll
                for (int jj = (kk == 64) ? 16 : (kk >> 1); jj > 0; jj >>= 1) {
                    bool lower = (lane & jj) == 0;
                    u64 o0 = __shfl_xor_sync(FULL, k0, jj);
                    u64 o1 = __shfl_xor_sync(FULL, k1, jj);
                    bool d0 = ((lane)      & kk) == 0;
                    bool d1 = ((lane + 32) & kk) == 0;
                    k0 = (lower == d0) ? max(k0, o0) : min(k0, o0);
                    k1 = (lower == d1) ? max(k1, o1) : min(k1, o1);
                }
            }
            float4 mb0 = bx4[(int)((k0 >> 8) & 0xFFFFFFull)];
            float4 mb1 = make_float4(0, 0, 0, 0);
            if (lane + 32 < cnt) mb1 = bx4[(int)((k1 >> 8) & 0xFFFFFFull)];
            bucket[wid * CAP + lane]      = k0;
            bucket[wid * CAP + lane + 32] = k1;
            sboxes[wid * CAP + lane]      = mb0;
            sboxes[wid * CAP + lane + 32] = mb1;
        }
        __syncwarp();

        // unified greedy loop: one broadcast LDS.128 per iteration
        for (int t = 0; t < cnt && kC < MAXO; t++) {
            float4 wb = sboxes[wid * CAP + t];
            float aW = (wb.z - wb.x) * (wb.w - wb.y);
            bool sup = false;
            if (lane < kC) {
                float ltx = fmaxf(kx1, wb.x), lty = fmaxf(ky1, wb.y);
                float rbx = fminf(kx2, wb.z), rby = fminf(ky2, wb.w);
                float inter = fmaxf(rbx - ltx, 0.0f) * fmaxf(rby - lty, 0.0f);
                sup = inter / (karea + aW - inter + 1e-9f) > NMS_THRESH;
            }
            if (!__any_sync(FULL, sup)) {
                if (lane == kC) { kx1 = wb.x; ky1 = wb.y; kx2 = wb.z; ky2 = wb.w;
                                  karea = aW; myT = t; }
                kC++;
            }
        }
    }

    if (vc) {
        bool v = (myT >= 0);
        u64 mykey = v ? bucket[wid * CAP + myT] : 0ull;   // single LDS
        if (c == 0) {
            if (lane < MAXH) {
                float* ob = outBoxes + ((size_t)b * KOUT + lane) * 4;
                *(float4*)ob = v ? make_float4(kx1, ky1, kx2, ky2)
                                 : make_float4(0, 0, 0, 0);
                outScores[b * KOUT + lane] = v ? __uint_as_float((unsigned)(mykey >> 32)) : 0.0f;
                outLabels[b * KOUT + lane] = v ? 0.0f : -1.0f;
                outValid [b * KOUT + lane] = v ? 1.0f : 0.0f;
            }
        } else {
            if (lane < MAXO)
                g_keys[((size_t)b * NCLS + c) * MAXO + lane] = mykey;
        }
    }

    // ---- last-CTA election (threadFenceReduction pattern) ----
    __syncthreads();
    if (tid == 0) {
        __threadfence();
        unsigned old = atomicAdd(&g_done[b], 1u);
        isLast = ((old & (G - 1)) == (G - 1)) ? 1 : 0;
        if (isLast) __threadfence();
    }
    __syncthreads();
    if (!isLast) return;

    // ---- merge (last CTA): stage 1200 keys, redux tournament top-15 ----
    const size_t bb = (size_t)b * NCLS * MAXO;
    for (int i = tid; i < NOKEYS; i += NTHREADS) allkeys[i] = g_keys[bb + MAXO + i];
    __syncthreads();

    if (tid < 32) {
        const int l0 = lane, l1 = lane + 32, l2 = lane + 64;
        u64 h0 = allkeys[l0 * MAXO];
        u64 h1 = allkeys[l1 * MAXO];
        u64 h2 = (lane < 16) ? allkeys[l2 * MAXO] : 0ull;
        int p0 = 0, p1 = 0, p2 = 0;

        u64 mkey = 0;
        for (int r = 0; r < MAXO; r++) {
            u64 lmax = max(h0, max(h1, h2));
            unsigned hi = (unsigned)(lmax >> 32);
            unsigned mh = __reduce_max_sync(FULL, hi);
            unsigned lo = (hi == mh) ? (unsigned)lmax : 0u;
            unsigned ml = __reduce_max_sync(FULL, lo);
            u64 win = ((u64)mh << 32) | ml;
            if (win == 0ull) break;
            if (lane == r) mkey = win;
            if (h0 == win)      { p0++; h0 = (p0 < MAXO) ? allkeys[l0 * MAXO + p0] : 0ull; }
            else if (h1 == win) { p1++; h1 = (p1 < MAXO) ? allkeys[l1 * MAXO + p1] : 0ull; }
            else if (h2 == win) { p2++; h2 = (p2 < MAXO) ? allkeys[l2 * MAXO + p2] : 0ull; }
        }

        if (lane < MAXO) {
            int slot = MAXH + lane;
            bool v = (mkey != 0ull);
            float4 wb = v ? bx4[(int)((mkey >> 8) & 0xFFFFFFull)]
                          : make_float4(0, 0, 0, 0);
            float* ob = outBoxes + ((size_t)b * KOUT + slot) * 4;
            *(float4*)ob = wb;
            outScores[b * KOUT + slot] = v ? __uint_as_float((unsigned)(mkey >> 32)) : 0.0f;
            outLabels[b * KOUT + slot] = v ? (float)(int)(mkey & 0xFFull) : -1.0f;
            outValid [b * KOUT + slot] = v ? 1.0f : 0.0f;
        }
    }
}

extern "C" void kernel_launch(void* const* d_in, const int* in_sizes, int n_in,
                              void* d_out, int out_size)
{
    const float* boxes  = (const float*)d_in[0];
    const float* scores = (const float*)d_in[1];
    const int*   labels = (const int*)d_in[2];

    int B = out_size / (KOUT * 7);        // 32
    if (B <= 0) B = 1;
    if (B > BMAX) B = BMAX;
    int N = in_sizes[1] / B;              // 2048

    dim3 grid(G, B);
    fused_kernel<<<grid, NTHREADS>>>(boxes, scores, labels, (float*)d_out, B, N);
}